// round 2
// baseline (speedup 1.0000x reference)
#include <cuda_runtime.h>

// Problem constants
#define NB     8
#define NH     16
#define NS     2048
#define DD     64
#define HI     256
#define NITN   4
#define CHUNK  512
#define MT     32
#define NTILE  (CHUNK / MT)          // 16
#define INV_SC (1.0f / 32768.0f)     // 1/(chunk*D)

// Final adapted weights per (b,h): [128][W1(64*256) | W2(256*64)]
__device__ float g_W[NB * NH * (DD * HI + HI * DD)];

// ---------------- gelu (tanh approximation, matches jax.nn.gelu default) ----
__device__ __forceinline__ float gelu_fwd_bwd(float x, float* dg) {
    const float c0 = 0.7978845608028654f;   // sqrt(2/pi)
    const float a0 = 0.044715f;
    float x2 = x * x;
    float u  = c0 * x * fmaf(a0, x2, 1.0f);
    float t  = tanhf(u);
    float du = c0 * fmaf(3.0f * a0, x2, 1.0f);
    *dg = 0.5f * (1.0f + t) + 0.5f * x * (1.0f - t * t) * du;
    return 0.5f * x * (1.0f + t);
}
__device__ __forceinline__ float gelu_f(float x) {
    const float c0 = 0.7978845608028654f;
    const float a0 = 0.044715f;
    float u = c0 * x * fmaf(a0, x * x, 1.0f);
    return 0.5f * x * (1.0f + tanhf(u));
}

// ---------------- SMEM layout (floats), training kernel ---------------------
// sW1 : [64][256]          @ 0      (16384)
// sW2 : [256][65] (padded) @ 16384  (16640)
// sZ  : [32][256] Z->H->dZ @ 33024  (8192)
// sGp : [32][256] gelu'    @ 41216  (8192)
// sX  : [32][64]           @ 49408  (2048)
// sY  : [32][64]           @ 51456  (2048)
// sE  : [32][64]           @ 53504  (2048)
// total 55552 floats = 222208 bytes
#define TRAIN_SMEM_BYTES 222208
#define EVAL_SMEM_BYTES  212992

__global__ __launch_bounds__(256, 1)
void ttt_train_kernel(const float* __restrict__ kk, const float* __restrict__ vv,
                      const float* __restrict__ W1g, const float* __restrict__ W2g) {
    extern __shared__ float sm[];
    float* sW1 = sm;              // [64][256]
    float* sW2 = sm + 16384;      // [256][65]
    float* sZ  = sm + 33024;      // [32][256]
    float* sGp = sm + 41216;      // [32][256]
    float* sX  = sm + 49408;      // [32][64]
    float* sY  = sm + 51456;      // [32][64]
    float* sE  = sm + 53504;      // [32][64]

    const int bh   = blockIdx.x;        // b*NH + h
    const int h    = bh & (NH - 1);
    const int tid  = threadIdx.x;
    const int lane = tid & 31;
    const int rg   = tid >> 5;          // 0..7

    // Load initial weights (same for every b)
    const float* gW1 = W1g + (size_t)h * DD * HI;
    const float* gW2 = W2g + (size_t)h * HI * DD;
    for (int i = tid; i < DD * HI; i += 256) sW1[i] = gW1[i];
    for (int i = tid; i < HI * DD; i += 256) {
        int e = i >> 6, o = i & 63;
        sW2[e * 65 + o] = gW2[i];
    }
    __syncthreads();

    const float* kb = kk + (size_t)bh * NS * DD;
    const float* vb = vv + (size_t)bh * NS * DD;

    // Gradient accumulators (registers)
    // dW1a: d = rg*8+i (i<8), e = lane+32*j (j<8)
    // dW2a: e = rg*32+je (je<32), o = lane+32*jo (jo<2)
    float dW1a[8][8];
    float dW2a[32][2];

    for (int it = 0; it < NITN; ++it) {
        #pragma unroll
        for (int i = 0; i < 8; ++i)
            #pragma unroll
            for (int j = 0; j < 8; ++j) dW1a[i][j] = 0.0f;
        #pragma unroll
        for (int je = 0; je < 32; ++je) { dW2a[je][0] = 0.0f; dW2a[je][1] = 0.0f; }

        for (int mt = 0; mt < NTILE; ++mt) {
            const int rowbase = it * CHUNK + mt * MT;
            // Load X (k) and Y (v) tiles: contiguous 2048 floats each
            #pragma unroll
            for (int r = 0; r < 8; ++r) {
                sX[tid + 256 * r] = kb[(size_t)rowbase * DD + tid + 256 * r];
                sY[tid + 256 * r] = vb[(size_t)rowbase * DD + tid + 256 * r];
            }
            __syncthreads();

            // ---- G1: Z[32][256] = X @ W1 ; rows m=rg*4+i, cols e=lane+32*j
            {
                float acc[4][8];
                #pragma unroll
                for (int i = 0; i < 4; ++i)
                    #pragma unroll
                    for (int j = 0; j < 8; ++j) acc[i][j] = 0.0f;
                #pragma unroll 4
                for (int d = 0; d < DD; ++d) {
                    float a[4];
                    #pragma unroll
                    for (int i = 0; i < 4; ++i) a[i] = sX[(rg * 4 + i) * DD + d];
                    float b[8];
                    #pragma unroll
                    for (int j = 0; j < 8; ++j) b[j] = sW1[d * HI + lane + 32 * j];
                    #pragma unroll
                    for (int i = 0; i < 4; ++i)
                        #pragma unroll
                        for (int j = 0; j < 8; ++j)
                            acc[i][j] = fmaf(a[i], b[j], acc[i][j]);
                }
                #pragma unroll
                for (int i = 0; i < 4; ++i)
                    #pragma unroll
                    for (int j = 0; j < 8; ++j) {
                        float gp;
                        float hv = gelu_fwd_bwd(acc[i][j], &gp);
                        int idx = (rg * 4 + i) * HI + lane + 32 * j;
                        sZ[idx]  = hv;     // store H
                        sGp[idx] = gp;     // store gelu'
                    }
            }
            __syncthreads();

            // ---- G2: E[32][64] = (H @ W2 - Y) * INV_SC
            {
                float acc[4][2];
                #pragma unroll
                for (int i = 0; i < 4; ++i) { acc[i][0] = 0.0f; acc[i][1] = 0.0f; }
                #pragma unroll 4
                for (int e = 0; e < HI; ++e) {
                    float a[4];
                    #pragma unroll
                    for (int i = 0; i < 4; ++i) a[i] = sZ[(rg * 4 + i) * HI + e];
                    float b0 = sW2[e * 65 + lane];
                    float b1 = sW2[e * 65 + lane + 32];
                    #pragma unroll
                    for (int i = 0; i < 4; ++i) {
                        acc[i][0] = fmaf(a[i], b0, acc[i][0]);
                        acc[i][1] = fmaf(a[i], b1, acc[i][1]);
                    }
                }
                #pragma unroll
                for (int i = 0; i < 4; ++i) {
                    int m = rg * 4 + i;
                    sE[m * DD + lane]      = (acc[i][0] - sY[m * DD + lane])      * INV_SC;
                    sE[m * DD + lane + 32] = (acc[i][1] - sY[m * DD + lane + 32]) * INV_SC;
                }
            }
            __syncthreads();

            // ---- G3: dW2 += H^T @ E  (K = 32 rows)
            #pragma unroll 2
            for (int m = 0; m < MT; ++m) {
                float b0 = sE[m * DD + lane];
                float b1 = sE[m * DD + lane + 32];
                #pragma unroll
                for (int je = 0; je < 32; ++je) {
                    float a = sZ[m * HI + rg * 32 + je];
                    dW2a[je][0] = fmaf(a, b0, dW2a[je][0]);
                    dW2a[je][1] = fmaf(a, b1, dW2a[je][1]);
                }
            }

            // ---- G4: dH[32][256] = E @ W2^T ; dZ = dH * gelu'
            {
                float dz[4][8];
                #pragma unroll
                for (int i = 0; i < 4; ++i)
                    #pragma unroll
                    for (int j = 0; j < 8; ++j) dz[i][j] = 0.0f;
                #pragma unroll 4
                for (int o = 0; o < DD; ++o) {
                    float a[4];
                    #pragma unroll
                    for (int i = 0; i < 4; ++i) a[i] = sE[(rg * 4 + i) * DD + o];
                    float b[8];
                    #pragma unroll
                    for (int j = 0; j < 8; ++j) b[j] = sW2[(lane + 32 * j) * 65 + o];
                    #pragma unroll
                    for (int i = 0; i < 4; ++i)
                        #pragma unroll
                        for (int j = 0; j < 8; ++j)
                            dz[i][j] = fmaf(a[i], b[j], dz[i][j]);
                }
                __syncthreads();   // G3 finished reading sZ(H); now overwrite with dZ
                #pragma unroll
                for (int i = 0; i < 4; ++i)
                    #pragma unroll
                    for (int j = 0; j < 8; ++j) {
                        int idx = (rg * 4 + i) * HI + lane + 32 * j;
                        sZ[idx] = dz[i][j] * sGp[idx];
                    }
            }
            __syncthreads();

            // ---- G5: dW1 += X^T @ dZ  (K = 32 rows)
            #pragma unroll 2
            for (int m = 0; m < MT; ++m) {
                float a[8];
                #pragma unroll
                for (int i = 0; i < 8; ++i) a[i] = sX[m * DD + rg * 8 + i];
                float b[8];
                #pragma unroll
                for (int j = 0; j < 8; ++j) b[j] = sZ[m * HI + lane + 32 * j];
                #pragma unroll
                for (int i = 0; i < 8; ++i)
                    #pragma unroll
                    for (int j = 0; j < 8; ++j)
                        dW1a[i][j] = fmaf(a[i], b[j], dW1a[i][j]);
            }
            __syncthreads();   // protect sX/sY/sZ before next tile
        }

        // ---- SGD update (lr = 1.0)
        #pragma unroll
        for (int i = 0; i < 8; ++i)
            #pragma unroll
            for (int j = 0; j < 8; ++j)
                sW1[(rg * 8 + i) * HI + lane + 32 * j] -= dW1a[i][j];
        #pragma unroll
        for (int je = 0; je < 32; ++je) {
            sW2[(rg * 32 + je) * 65 + lane]      -= dW2a[je][0];
            sW2[(rg * 32 + je) * 65 + lane + 32] -= dW2a[je][1];
        }
        __syncthreads();
    }

    // Store final adapted weights to scratch
    float* gw = g_W + (size_t)bh * (DD * HI + HI * DD);
    for (int i = tid; i < DD * HI; i += 256) gw[i] = sW1[i];
    for (int i = tid; i < HI * DD; i += 256) {
        int e = i >> 6, o = i & 63;
        gw[DD * HI + i] = sW2[e * 65 + o];
    }
}

// ---------------- Eval: out = enc(final_params, q), 64-row tiles ------------
// SMEM: sW1 [64][256] @0 (16384), sW2 [256][64] @16384 (16384),
//       sQ [64][64] @32768 (4096), sH [64][256] @36864 (16384) -> 53248 floats
__global__ __launch_bounds__(256, 1)
void ttt_eval_kernel(const float* __restrict__ qq, float* __restrict__ out) {
    extern __shared__ float sm[];
    float* sW1 = sm;
    float* sW2 = sm + 16384;
    float* sQ  = sm + 32768;
    float* sH  = sm + 36864;

    const int tile = blockIdx.x;     // 0..31
    const int bh   = blockIdx.y;     // 0..127
    const int b    = bh >> 4;
    const int h    = bh & 15;
    const int tid  = threadIdx.x;
    const int lane = tid & 31;
    const int rg   = tid >> 5;

    const float* gw = g_W + (size_t)bh * (DD * HI + HI * DD);
    for (int i = tid; i < DD * HI; i += 256) sW1[i] = gw[i];
    for (int i = tid; i < HI * DD; i += 256) sW2[i] = gw[DD * HI + i];

    const float* qb = qq + ((size_t)bh * NS + tile * 64) * DD;
    for (int i = tid; i < 64 * DD; i += 256) sQ[i] = qb[i];
    __syncthreads();

    // Z[64][256] = Q @ W1 ; rows m=rg*8+i, cols e=lane+32*j
    {
        float acc[8][8];
        #pragma unroll
        for (int i = 0; i < 8; ++i)
            #pragma unroll
            for (int j = 0; j < 8; ++j) acc[i][j] = 0.0f;
        #pragma unroll 4
        for (int d = 0; d < DD; ++d) {
            float a[8];
            #pragma unroll
            for (int i = 0; i < 8; ++i) a[i] = sQ[(rg * 8 + i) * DD + d];
            float bvals[8];
            #pragma unroll
            for (int j = 0; j < 8; ++j) bvals[j] = sW1[d * HI + lane + 32 * j];
            #pragma unroll
            for (int i = 0; i < 8; ++i)
                #pragma unroll
                for (int j = 0; j < 8; ++j)
                    acc[i][j] = fmaf(a[i], bvals[j], acc[i][j]);
        }
        #pragma unroll
        for (int i = 0; i < 8; ++i)
            #pragma unroll
            for (int j = 0; j < 8; ++j)
                sH[(rg * 8 + i) * HI + lane + 32 * j] = gelu_f(acc[i][j]);
    }
    __syncthreads();

    // O[64][64] = H @ W2 ; rows m=rg*8+i, cols o=lane+32*jo
    {
        float acc[8][2];
        #pragma unroll
        for (int i = 0; i < 8; ++i) { acc[i][0] = 0.0f; acc[i][1] = 0.0f; }
        #pragma unroll 4
        for (int e = 0; e < HI; ++e) {
            float a[8];
            #pragma unroll
            for (int i = 0; i < 8; ++i) a[i] = sH[(rg * 8 + i) * HI + e];
            float b0 = sW2[e * DD + lane];
            float b1 = sW2[e * DD + lane + 32];
            #pragma unroll
            for (int i = 0; i < 8; ++i) {
                acc[i][0] = fmaf(a[i], b0, acc[i][0]);
                acc[i][1] = fmaf(a[i], b1, acc[i][1]);
            }
        }
        // out[b, n, h*64 + o], n = tile*64 + m
        #pragma unroll
        for (int i = 0; i < 8; ++i) {
            int n = tile * 64 + rg * 8 + i;
            size_t base = ((size_t)b * NS + n) * (NH * DD) + h * DD;
            out[base + lane]      = acc[i][0];
            out[base + lane + 32] = acc[i][1];
        }
    }
}

extern "C" void kernel_launch(void* const* d_in, const int* in_sizes, int n_in,
                              void* d_out, int out_size) {
    const float* q  = (const float*)d_in[0];
    const float* k  = (const float*)d_in[1];
    const float* v  = (const float*)d_in[2];
    const float* W1 = (const float*)d_in[3];
    const float* W2 = (const float*)d_in[4];
    float* out = (float*)d_out;

    cudaFuncSetAttribute(ttt_train_kernel,
                         cudaFuncAttributeMaxDynamicSharedMemorySize, TRAIN_SMEM_BYTES);
    cudaFuncSetAttribute(ttt_eval_kernel,
                         cudaFuncAttributeMaxDynamicSharedMemorySize, EVAL_SMEM_BYTES);

    ttt_train_kernel<<<NB * NH, 256, TRAIN_SMEM_BYTES>>>(k, v, W1, W2);
    ttt_eval_kernel<<<dim3(NS / 64, NB * NH), 256, EVAL_SMEM_BYTES>>>(q, out);
}

// round 4
// speedup vs baseline: 1.1772x; 1.1772x over previous
#include <cuda_runtime.h>

// Problem constants
#define NB     8
#define NH     16
#define NS     2048
#define DD     64
#define HI     256
#define NITN   4
#define CHUNK  512
#define MT     32
#define NTILE  (CHUNK / MT)          // 16
#define INV_SC (1.0f / 32768.0f)     // 1/(chunk*D)

typedef unsigned long long U64;

// Final adapted weights per (b,h): [128][W1(64*256) | W2(256*64)]
__device__ float g_W[NB * NH * (DD * HI + HI * DD)];

// ---------------- packed f32x2 helpers --------------------------------------
__device__ __forceinline__ U64 ld64s(const float* p) {
    return *reinterpret_cast<const U64*>(p);
}
__device__ __forceinline__ void st64s(float* p, U64 v) {
    *reinterpret_cast<U64*>(p) = v;
}
__device__ __forceinline__ U64 pack2(float lo, float hi) {
    U64 r; asm("mov.b64 %0, {%1, %2};" : "=l"(r) : "f"(lo), "f"(hi)); return r;
}
__device__ __forceinline__ float2 unp2(U64 v) {
    float2 f; asm("mov.b64 {%0, %1}, %2;" : "=f"(f.x), "=f"(f.y) : "l"(v)); return f;
}
__device__ __forceinline__ U64 ffma2(U64 a, U64 b, U64 c) {
    U64 d; asm("fma.rn.f32x2 %0, %1, %2, %3;" : "=l"(d) : "l"(a), "l"(b), "l"(c));
    return d;
}

// ---------------- gelu (tanh approximation, matches jax.nn.gelu) ------------
__device__ __forceinline__ float gelu_fwd_bwd(float x, float* dg) {
    const float c0 = 0.7978845608028654f;
    const float a0 = 0.044715f;
    float x2 = x * x;
    float u  = c0 * x * fmaf(a0, x2, 1.0f);
    float t  = tanhf(u);
    float du = c0 * fmaf(3.0f * a0, x2, 1.0f);
    *dg = 0.5f * (1.0f + t) + 0.5f * x * (1.0f - t * t) * du;
    return 0.5f * x * (1.0f + t);
}
__device__ __forceinline__ float gelu_f(float x) {
    const float c0 = 0.7978845608028654f;
    const float a0 = 0.044715f;
    float u = c0 * x * fmaf(a0, x * x, 1.0f);
    return 0.5f * x * (1.0f + tanhf(u));
}

// ---------------- training smem layout (floats) -----------------------------
// sW1 [64][256]      @ 0      16384
// sW2 [256][66] pad  @ 16384  16896
// sGp [32][256]      @ 33280   8192
// sH  [32][256]      @ 41472   8192   (H, later overwritten with dZ)
// sXd [32][128] dup  @ 49664   4096   ({x,x} pairs)
// sE  [32][64]       @ 53760   2048
#define OFF_W1  0
#define OFF_W2  16384
#define OFF_GP  33280
#define OFF_H   41472
#define OFF_XD  49664
#define OFF_E   53760
#define TRAIN_SMEM_BYTES (55808 * 4)

__global__ __launch_bounds__(256, 1)
void ttt_train_kernel(const float* __restrict__ kk, const float* __restrict__ vv,
                      const float* __restrict__ W1g, const float* __restrict__ W2g) {
    extern __shared__ float sm[];
    float* sW1 = sm + OFF_W1;
    float* sW2 = sm + OFF_W2;   // stride 66
    float* sGp = sm + OFF_GP;
    float* sH  = sm + OFF_H;
    float* sXd = sm + OFF_XD;
    float* sE  = sm + OFF_E;

    const int bh   = blockIdx.x;
    const int h    = bh & (NH - 1);
    const int tid  = threadIdx.x;
    const int lane = tid & 31;
    const int rg   = tid >> 5;          // 0..7
    const int o2   = tid & 63;          // G2 column
    const int mg   = (tid >> 6) * 8;    // G2 row group

    const float* gW1 = W1g + (size_t)h * DD * HI;
    const float* gW2 = W2g + (size_t)h * HI * DD;
    for (int i = tid; i < DD * HI; i += 256) sW1[i] = gW1[i];
    for (int i = tid; i < HI * DD; i += 256) {
        int e = i >> 6, o = i & 63;
        sW2[e * 66 + o] = gW2[i];
    }
    __syncthreads();

    const float* kb = kk + (size_t)bh * NS * DD;
    const float* vb = vv + (size_t)bh * NS * DD;

    // Persistent gradient accumulators (packed pairs)
    U64 dW1a[8][4];   // d = rg*8+i ; e-pair jp -> cols {2(lane+32jp), +1}
    U64 dW2a[16][2];  // e-pair pe: rows {rg*32+2pe, +1}; o = lane+32c

    for (int it = 0; it < NITN; ++it) {
        #pragma unroll
        for (int i = 0; i < 8; ++i)
            #pragma unroll
            for (int jp = 0; jp < 4; ++jp) dW1a[i][jp] = 0ull;
        #pragma unroll
        for (int pe = 0; pe < 16; ++pe) { dW2a[pe][0] = 0ull; dW2a[pe][1] = 0ull; }

        for (int mt = 0; mt < NTILE; ++mt) {
            const int rowbase = it * CHUNK + mt * MT;

            // prefetch Y for the G2 epilogue (rows mg+i, col o2)
            float yv[8];
            #pragma unroll
            for (int i = 0; i < 8; ++i)
                yv[i] = vb[(size_t)(rowbase + mg + i) * DD + o2];

            // load X tile, store duplicated {x,x}
            #pragma unroll
            for (int r = 0; r < 8; ++r) {
                int f = tid + 256 * r;
                float x = kb[(size_t)rowbase * DD + f];
                st64s(&sXd[2 * f], pack2(x, x));
            }
            __syncthreads();

            // ---- G1: Z = X @ W1. rows rg*4+i, col-pairs lane+32jp
            {
                U64 acc[4][4];
                #pragma unroll
                for (int i = 0; i < 4; ++i)
                    #pragma unroll
                    for (int jp = 0; jp < 4; ++jp) acc[i][jp] = 0ull;
                #pragma unroll 4
                for (int d2 = 0; d2 < 32; ++d2) {      // 2 d per iter
                    ulonglong2 aa[4];
                    #pragma unroll
                    for (int i = 0; i < 4; ++i)
                        aa[i] = *reinterpret_cast<const ulonglong2*>(
                            &sXd[(rg * 4 + i) * 128 + 4 * d2]);
                    U64 b0[4], b1[4];
                    #pragma unroll
                    for (int jp = 0; jp < 4; ++jp) {
                        b0[jp] = ld64s(&sW1[(2 * d2) * HI + 2 * (lane + 32 * jp)]);
                        b1[jp] = ld64s(&sW1[(2 * d2 + 1) * HI + 2 * (lane + 32 * jp)]);
                    }
                    #pragma unroll
                    for (int i = 0; i < 4; ++i)
                        #pragma unroll
                        for (int jp = 0; jp < 4; ++jp) {
                            acc[i][jp] = ffma2(aa[i].x, b0[jp], acc[i][jp]);
                            acc[i][jp] = ffma2(aa[i].y, b1[jp], acc[i][jp]);
                        }
                }
                #pragma unroll
                for (int i = 0; i < 4; ++i)
                    #pragma unroll
                    for (int jp = 0; jp < 4; ++jp) {
                        float2 z = unp2(acc[i][jp]);
                        float g0, g1;
                        float h0 = gelu_fwd_bwd(z.x, &g0);
                        float h1 = gelu_fwd_bwd(z.y, &g1);
                        int idx = (rg * 4 + i) * HI + 2 * (lane + 32 * jp);
                        st64s(&sH[idx],  pack2(h0, h1));
                        st64s(&sGp[idx], pack2(g0, g1));
                    }
            }
            __syncthreads();

            // ---- G2: E = (H @ W2 - Y) * INV_SC. rows mg+i, col o2, K-pairs over e
            {
                U64 eacc[8];
                #pragma unroll
                for (int i = 0; i < 8; ++i) eacc[i] = 0ull;
                #pragma unroll 2
                for (int ep2 = 0; ep2 < 64; ++ep2) {   // 4 e per iter
                    float w0 = sW2[(4 * ep2 + 0) * 66 + o2];
                    float w1 = sW2[(4 * ep2 + 1) * 66 + o2];
                    float w2 = sW2[(4 * ep2 + 2) * 66 + o2];
                    float w3 = sW2[(4 * ep2 + 3) * 66 + o2];
                    U64 b0 = pack2(w0, w1), b1 = pack2(w2, w3);
                    #pragma unroll
                    for (int i = 0; i < 8; ++i) {
                        ulonglong2 a = *reinterpret_cast<const ulonglong2*>(
                            &sH[(mg + i) * HI + 4 * ep2]);
                        eacc[i] = ffma2(a.x, b0, eacc[i]);
                        eacc[i] = ffma2(a.y, b1, eacc[i]);
                    }
                }
                #pragma unroll
                for (int i = 0; i < 8; ++i) {
                    float2 s = unp2(eacc[i]);
                    sE[(mg + i) * DD + o2] = (s.x + s.y - yv[i]) * INV_SC;
                }
            }
            __syncthreads();

            // ---- G3: dW2 += H^T @ E  (e-pairs rg*32+2pe, o = lane+32c)
            #pragma unroll 2
            for (int m = 0; m < MT; ++m) {
                float e0 = sE[m * DD + lane];
                float e1 = sE[m * DD + lane + 32];
                U64 b0 = pack2(e0, e0);
                U64 b1 = pack2(e1, e1);
                #pragma unroll
                for (int pe2 = 0; pe2 < 8; ++pe2) {    // 4 e per iter
                    ulonglong2 a = *reinterpret_cast<const ulonglong2*>(
                        &sH[m * HI + rg * 32 + 4 * pe2]);
                    dW2a[2 * pe2][0]     = ffma2(a.x, b0, dW2a[2 * pe2][0]);
                    dW2a[2 * pe2][1]     = ffma2(a.x, b1, dW2a[2 * pe2][1]);
                    dW2a[2 * pe2 + 1][0] = ffma2(a.y, b0, dW2a[2 * pe2 + 1][0]);
                    dW2a[2 * pe2 + 1][1] = ffma2(a.y, b1, dW2a[2 * pe2 + 1][1]);
                }
            }

            // ---- G4: dH = E @ W2^T ; dZ = dH * gelu'. col e = tid, 2 halves of 16 rows
            {
                #pragma unroll
                for (int half = 0; half < 2; ++half) {
                    const int mb = half * 16;
                    U64 g4[16];
                    #pragma unroll
                    for (int m = 0; m < 16; ++m) g4[m] = 0ull;
                    #pragma unroll 2
                    for (int op2 = 0; op2 < 16; ++op2) {   // 4 o per iter
                        U64 b0 = ld64s(&sW2[tid * 66 + 4 * op2]);
                        U64 b1 = ld64s(&sW2[tid * 66 + 4 * op2 + 2]);
                        #pragma unroll
                        for (int m = 0; m < 16; ++m) {
                            ulonglong2 a = *reinterpret_cast<const ulonglong2*>(
                                &sE[(mb + m) * DD + 4 * op2]);
                            g4[m] = ffma2(a.x, b0, g4[m]);
                            g4[m] = ffma2(a.y, b1, g4[m]);
                        }
                    }
                    if (half == 0) __syncthreads();  // all G3 reads of sH done
                    #pragma unroll
                    for (int m = 0; m < 16; ++m) {
                        float2 s = unp2(g4[m]);
                        int idx = (mb + m) * HI + tid;
                        sH[idx] = (s.x + s.y) * sGp[idx];
                    }
                }
            }
            __syncthreads();

            // ---- G5: dW1 += X^T @ dZ  (d = rg*8+i, e-pairs lane+32jp)
            #pragma unroll 2
            for (int m = 0; m < MT; ++m) {
                ulonglong2 aa[4];
                #pragma unroll
                for (int ii = 0; ii < 4; ++ii)
                    aa[ii] = *reinterpret_cast<const ulonglong2*>(
                        &sXd[m * 128 + 16 * rg + 4 * ii]);
                U64 b[4];
                #pragma unroll
                for (int jp = 0; jp < 4; ++jp)
                    b[jp] = ld64s(&sH[m * HI + 2 * (lane + 32 * jp)]);
                #pragma unroll
                for (int ii = 0; ii < 4; ++ii)
                    #pragma unroll
                    for (int jp = 0; jp < 4; ++jp) {
                        dW1a[2 * ii][jp]     = ffma2(aa[ii].x, b[jp], dW1a[2 * ii][jp]);
                        dW1a[2 * ii + 1][jp] = ffma2(aa[ii].y, b[jp], dW1a[2 * ii + 1][jp]);
                    }
            }
            __syncthreads();   // protect sXd/sH/sE before next tile
        }

        // ---- SGD update (lr = 1.0)
        #pragma unroll
        for (int i = 0; i < 8; ++i)
            #pragma unroll
            for (int jp = 0; jp < 4; ++jp) {
                int addr = (rg * 8 + i) * HI + 2 * (lane + 32 * jp);
                float2 w = unp2(ld64s(&sW1[addr]));
                float2 g = unp2(dW1a[i][jp]);
                st64s(&sW1[addr], pack2(w.x - g.x, w.y - g.y));
            }
        #pragma unroll
        for (int pe = 0; pe < 16; ++pe) {
            int e = rg * 32 + 2 * pe;
            #pragma unroll
            for (int c = 0; c < 2; ++c) {
                float2 g = unp2(dW2a[pe][c]);
                int o = lane + 32 * c;
                sW2[e * 66 + o]       -= g.x;
                sW2[(e + 1) * 66 + o] -= g.y;
            }
        }
        __syncthreads();
    }

    // Store final adapted weights
    float* gw = g_W + (size_t)bh * (DD * HI + HI * DD);
    for (int i = tid; i < DD * HI; i += 256) gw[i] = sW1[i];
    for (int i = tid; i < HI * DD; i += 256) {
        int e = i >> 6, o = i & 63;
        gw[DD * HI + i] = sW2[e * 66 + o];
    }
}

// ---------------- eval: e-chunked fused MLP, occupancy 2 --------------------
// smem (floats): sQd [64][128] dup @0 (8192) | sW1c [64][64] @8192 (4096) |
//                sW2c [64][64] @12288 (4096) | sHc [64][64] @16384 (4096)
// total 20480 floats = 81920 bytes -> 2 CTAs/SM
#define EOFF_QD  0
#define EOFF_W1C 8192
#define EOFF_W2C 12288
#define EOFF_HC  16384
#define EVAL_SMEM_BYTES (20480 * 4)

__global__ __launch_bounds__(256, 2)
void ttt_eval_kernel(const float* __restrict__ qq, float* __restrict__ out) {
    extern __shared__ float sm[];
    float* sQd  = sm + EOFF_QD;
    float* sW1c = sm + EOFF_W1C;
    float* sW2c = sm + EOFF_W2C;
    float* sHc  = sm + EOFF_HC;

    const int tile = blockIdx.x;     // 0..31
    const int bh   = blockIdx.y;     // 0..127
    const int b    = bh >> 4;
    const int h    = bh & 15;
    const int tid  = threadIdx.x;
    const int lane = tid & 31;
    const int rg   = tid >> 5;
    const int o2   = tid & 63;
    const int mg   = (tid >> 6) * 16;

    const float* gw = g_W + (size_t)bh * (DD * HI + HI * DD);
    const float* qb = qq + ((size_t)bh * NS + tile * 64) * DD;

    // load Q tile, duplicated {q,q}
    #pragma unroll
    for (int r = 0; r < 16; ++r) {
        int f = tid + 256 * r;
        float x = qb[f];
        st64s(&sQd[2 * f], pack2(x, x));
    }

    U64 oacc[16];    // rows mg+i, col o2; K-pair partials over e
    #pragma unroll
    for (int i = 0; i < 16; ++i) oacc[i] = 0ull;

    for (int c = 0; c < 4; ++c) {
        const int c0 = c * 64;
        __syncthreads();   // prev chunk consumers done (also covers sQd fill)
        // load W1 / W2 chunks (float4)
        #pragma unroll
        for (int r = 0; r < 4; ++r) {
            int i4 = tid + 256 * r;                 // 0..1023 float4's
            int dd = i4 >> 4, e4 = (i4 & 15) * 4;
            *reinterpret_cast<float4*>(&sW1c[dd * 64 + e4]) =
                *reinterpret_cast<const float4*>(&gw[dd * HI + c0 + e4]);
            int ee = i4 >> 4, o4 = (i4 & 15) * 4;
            *reinterpret_cast<float4*>(&sW2c[ee * 64 + o4]) =
                *reinterpret_cast<const float4*>(&gw[DD * HI + (c0 + ee) * 64 + o4]);
        }
        __syncthreads();

        // Z chunk: rows rg*8+i, col-pair lane (over 64 chunk cols)
        {
            U64 zacc[8];
            #pragma unroll
            for (int i = 0; i < 8; ++i) zacc[i] = 0ull;
            #pragma unroll 4
            for (int d2 = 0; d2 < 32; ++d2) {
                U64 b0 = ld64s(&sW1c[(2 * d2) * 64 + 2 * lane]);
                U64 b1 = ld64s(&sW1c[(2 * d2 + 1) * 64 + 2 * lane]);
                #pragma unroll
                for (int i = 0; i < 8; ++i) {
                    ulonglong2 a = *reinterpret_cast<const ulonglong2*>(
                        &sQd[(rg * 8 + i) * 128 + 4 * d2]);
                    zacc[i] = ffma2(a.x, b0, zacc[i]);
                    zacc[i] = ffma2(a.y, b1, zacc[i]);
                }
            }
            #pragma unroll
            for (int i = 0; i < 8; ++i) {
                float2 z = unp2(zacc[i]);
                st64s(&sHc[(rg * 8 + i) * 64 + 2 * lane],
                      pack2(gelu_f(z.x), gelu_f(z.y)));
            }
        }
        __syncthreads();

        // O partial: rows mg+i, col o2, K-pairs over chunk e
        #pragma unroll 2
        for (int ep2 = 0; ep2 < 16; ++ep2) {       // 4 e per iter
            float w0 = sW2c[(4 * ep2 + 0) * 64 + o2];
            float w1 = sW2c[(4 * ep2 + 1) * 64 + o2];
            float w2 = sW2c[(4 * ep2 + 2) * 64 + o2];
            float w3 = sW2c[(4 * ep2 + 3) * 64 + o2];
            U64 b0 = pack2(w0, w1), b1 = pack2(w2, w3);
            #pragma unroll
            for (int i = 0; i < 16; ++i) {
                ulonglong2 a = *reinterpret_cast<const ulonglong2*>(
                    &sHc[(mg + i) * 64 + 4 * ep2]);
                oacc[i] = ffma2(a.x, b0, oacc[i]);
                oacc[i] = ffma2(a.y, b1, oacc[i]);
            }
        }
    }

    // write out[b, n, h*64 + o]
    #pragma unroll
    for (int i = 0; i < 16; ++i) {
        float2 s = unp2(oacc[i]);
        int n = tile * 64 + mg + i;
        size_t base = ((size_t)b * NS + n) * (NH * DD) + h * DD;
        out[base + o2] = s.x + s.y;
    }
}

extern "C" void kernel_launch(void* const* d_in, const int* in_sizes, int n_in,
                              void* d_out, int out_size) {
    const float* q  = (const float*)d_in[0];
    const float* k  = (const float*)d_in[1];
    const float* v  = (const float*)d_in[2];
    const float* W1 = (const float*)d_in[3];
    const float* W2 = (const float*)d_in[4];
    float* out = (float*)d_out;

    cudaFuncSetAttribute(ttt_train_kernel,
                         cudaFuncAttributeMaxDynamicSharedMemorySize, TRAIN_SMEM_BYTES);
    cudaFuncSetAttribute(ttt_eval_kernel,
                         cudaFuncAttributeMaxDynamicSharedMemorySize, EVAL_SMEM_BYTES);

    ttt_train_kernel<<<NB * NH, 256, TRAIN_SMEM_BYTES>>>(k, v, W1, W2);
    ttt_eval_kernel<<<dim3(NS / 64, NB * NH), 256, EVAL_SMEM_BYTES>>>(q, out);
}

// round 6
// speedup vs baseline: 1.3115x; 1.1141x over previous
#include <cuda_runtime.h>

// Problem constants
#define NB     8
#define NH     16
#define NS     2048
#define DD     64
#define HI     256
#define NITN   4
#define CHUNK  512
#define MT     32
#define NTILE  (CHUNK / MT)          // 16
#define INV_SC (1.0f / 32768.0f)     // 1/(chunk*D)

typedef unsigned long long U64;

// Final adapted weights per (b,h): [128][ W1 pair-major 16384 | W2 pair-major 16384 ]
__device__ float g_W[NB * NH * (DD * HI + HI * DD)];

// ---------------- packed f32x2 helpers --------------------------------------
__device__ __forceinline__ U64 ld64s(const float* p) {
    return *reinterpret_cast<const U64*>(p);
}
__device__ __forceinline__ void st64s(float* p, U64 v) {
    *reinterpret_cast<U64*>(p) = v;
}
__device__ __forceinline__ U64 pack2(float lo, float hi) {
    U64 r; asm("mov.b64 %0, {%1, %2};" : "=l"(r) : "f"(lo), "f"(hi)); return r;
}
__device__ __forceinline__ float2 unp2(U64 v) {
    float2 f; asm("mov.b64 {%0, %1}, %2;" : "=f"(f.x), "=f"(f.y) : "l"(v)); return f;
}
__device__ __forceinline__ U64 ffma2(U64 a, U64 b, U64 c) {
    U64 d; asm("fma.rn.f32x2 %0, %1, %2, %3;" : "=l"(d) : "l"(a), "l"(b), "l"(c));
    return d;
}

// ---------------- fast accurate tanh (MUFU.EX2 + MUFU.RCP, ~1e-7 rel) -------
__device__ __forceinline__ float fast_tanh(float u) {
    float e = __expf(2.0f * u);
    return 1.0f - __fdividef(2.0f, e + 1.0f);
}

// ---------------- gelu (tanh approximation, matches jax.nn.gelu) ------------
__device__ __forceinline__ float gelu_fwd_bwd(float x, float* dg) {
    const float c0 = 0.7978845608028654f;
    const float a0 = 0.044715f;
    float x2 = x * x;
    float u  = c0 * x * fmaf(a0, x2, 1.0f);
    float t  = fast_tanh(u);
    float du = c0 * fmaf(3.0f * a0, x2, 1.0f);
    *dg = 0.5f * (1.0f + t) + 0.5f * x * (1.0f - t * t) * du;
    return 0.5f * x * (1.0f + t);
}
__device__ __forceinline__ float gelu_f(float x) {
    const float c0 = 0.7978845608028654f;
    const float a0 = 0.044715f;
    float u = c0 * x * fmaf(a0, x * x, 1.0f);
    return 0.5f * x * (1.0f + fast_tanh(u));
}

// ---------------- training smem layout (floats) -----------------------------
// sW1p [32 d2][256 e][2 s]  @ 0      16384   (W1[d][e] at (d>>1)*512 + e*2 + (d&1))
// sW2  [256][66]            @ 16384  16896
// sGp  [32][256]            @ 33280   8192
// sH   [32][256]            @ 41472   8192   (H, later overwritten with dZ)
// sX   [32][64]             @ 49664   2048
// sE   [32][64]             @ 51712   2048
#define OFF_W1P 0
#define OFF_W2  16384
#define OFF_GP  33280
#define OFF_H   41472
#define OFF_X   49664
#define OFF_E   51712
#define TRAIN_SMEM_BYTES (53760 * 4)

__global__ __launch_bounds__(256, 1)
void ttt_train_kernel(const float* __restrict__ kk, const float* __restrict__ vv,
                      const float* __restrict__ W1g, const float* __restrict__ W2g) {
    extern __shared__ float sm[];
    float* sW1p = sm + OFF_W1P;
    float* sW2  = sm + OFF_W2;   // stride 66
    float* sGp  = sm + OFF_GP;
    float* sH   = sm + OFF_H;
    float* sX   = sm + OFF_X;
    float* sE   = sm + OFF_E;

    const int bh   = blockIdx.x;
    const int h    = bh & (NH - 1);
    const int tid  = threadIdx.x;
    const int lane = tid & 31;
    const int rg   = tid >> 5;          // warp 0..7
    const int rb   = rg & 3;            // G1 row block
    const int ch   = rg >> 2;           // G1 col half
    const int o2   = tid & 63;          // G2 column
    const int mg   = (tid >> 6) * 8;    // G2 row group
    const int hr   = tid >> 7;          // G4 row half (0/1)
    const int c0   = tid & 127;         // G4 col base

    const float* gW1 = W1g + (size_t)h * DD * HI;
    const float* gW2 = W2g + (size_t)h * HI * DD;
    for (int i = tid; i < DD * HI; i += 256) {
        int d = i >> 8, e = i & 255;
        sW1p[(d >> 1) * 512 + e * 2 + (d & 1)] = gW1[i];
    }
    for (int i = tid; i < HI * DD; i += 256) {
        int e = i >> 6, o = i & 63;
        sW2[e * 66 + o] = gW2[i];
    }
    __syncthreads();

    const float* kb = kk + (size_t)bh * NS * DD;
    const float* vb = vv + (size_t)bh * NS * DD;

    // Persistent gradient accumulators
    U64 dW1a[4][8];   // d-pair p = rg*4+pp ; e = lane+32*j  -> {dW1[2p][e], dW1[2p+1][e]}
    U64 dW2a[16][2];  // e-pair pe: rows {rg*32+2pe, +1}; o = lane+32c

    for (int it = 0; it < NITN; ++it) {
        #pragma unroll
        for (int pp = 0; pp < 4; ++pp)
            #pragma unroll
            for (int j = 0; j < 8; ++j) dW1a[pp][j] = 0ull;
        #pragma unroll
        for (int pe = 0; pe < 16; ++pe) { dW2a[pe][0] = 0ull; dW2a[pe][1] = 0ull; }

        for (int mt = 0; mt < NTILE; ++mt) {
            const int rowbase = it * CHUNK + mt * MT;

            // prefetch Y for the G2 epilogue (rows mg+i, col o2)
            float yv[8];
            #pragma unroll
            for (int i = 0; i < 8; ++i)
                yv[i] = vb[(size_t)(rowbase + mg + i) * DD + o2];

            // load X tile (plain layout, float4)
            #pragma unroll
            for (int r = 0; r < 2; ++r) {
                int i4 = tid + 256 * r;
                *reinterpret_cast<float4*>(&sX[i4 * 4]) =
                    *reinterpret_cast<const float4*>(&kb[(size_t)rowbase * DD + i4 * 4]);
            }
            __syncthreads();

            // ---- G1: Z = X @ W1  (K-pair over d). rows rb*8..+8, 2 col passes
            #pragma unroll
            for (int pass = 0; pass < 2; ++pass) {
                const int e0 = lane + 32 * (ch * 4 + pass * 2);
                const int e1 = e0 + 32;
                U64 acc[8][2];
                #pragma unroll
                for (int r = 0; r < 8; ++r) { acc[r][0] = 0ull; acc[r][1] = 0ull; }
                #pragma unroll 4
                for (int dc = 0; dc < 16; ++dc) {     // 4 d per iter
                    ulonglong2 aa[8];
                    #pragma unroll
                    for (int r = 0; r < 8; ++r)
                        aa[r] = *reinterpret_cast<const ulonglong2*>(
                            &sX[(rb * 8 + r) * 64 + 4 * dc]);
                    U64 b00 = ld64s(&sW1p[(2 * dc) * 512 + e0 * 2]);
                    U64 b01 = ld64s(&sW1p[(2 * dc + 1) * 512 + e0 * 2]);
                    U64 b10 = ld64s(&sW1p[(2 * dc) * 512 + e1 * 2]);
                    U64 b11 = ld64s(&sW1p[(2 * dc + 1) * 512 + e1 * 2]);
                    #pragma unroll
                    for (int r = 0; r < 8; ++r) {
                        acc[r][0] = ffma2(aa[r].x, b00, acc[r][0]);
                        acc[r][0] = ffma2(aa[r].y, b01, acc[r][0]);
                        acc[r][1] = ffma2(aa[r].x, b10, acc[r][1]);
                        acc[r][1] = ffma2(aa[r].y, b11, acc[r][1]);
                    }
                }
                #pragma unroll
                for (int r = 0; r < 8; ++r)
                    #pragma unroll
                    for (int c = 0; c < 2; ++c) {
                        float2 s = unp2(acc[r][c]);
                        float z = s.x + s.y, gp;
                        float hv = gelu_fwd_bwd(z, &gp);
                        int idx = (rb * 8 + r) * HI + (c ? e1 : e0);
                        sH[idx]  = hv;
                        sGp[idx] = gp;
                    }
            }
            __syncthreads();

            // ---- G2: E = (H @ W2 - Y) * INV_SC. rows mg+i, col o2, K-pairs over e
            {
                U64 eacc[8];
                #pragma unroll
                for (int i = 0; i < 8; ++i) eacc[i] = 0ull;
                #pragma unroll 2
                for (int ep2 = 0; ep2 < 64; ++ep2) {   // 4 e per iter
                    float w0 = sW2[(4 * ep2 + 0) * 66 + o2];
                    float w1 = sW2[(4 * ep2 + 1) * 66 + o2];
                    float w2 = sW2[(4 * ep2 + 2) * 66 + o2];
                    float w3 = sW2[(4 * ep2 + 3) * 66 + o2];
                    U64 b0 = pack2(w0, w1), b1 = pack2(w2, w3);
                    #pragma unroll
                    for (int i = 0; i < 8; ++i) {
                        ulonglong2 a = *reinterpret_cast<const ulonglong2*>(
                            &sH[(mg + i) * HI + 4 * ep2]);
                        eacc[i] = ffma2(a.x, b0, eacc[i]);
                        eacc[i] = ffma2(a.y, b1, eacc[i]);
                    }
                }
                #pragma unroll
                for (int i = 0; i < 8; ++i) {
                    float2 s = unp2(eacc[i]);
                    sE[(mg + i) * DD + o2] = (s.x + s.y - yv[i]) * INV_SC;
                }
            }
            __syncthreads();

            // ---- G3: dW2 += H^T @ E  (e-pairs rg*32+2pe, o = lane+32c)
            #pragma unroll 2
            for (int m = 0; m < MT; ++m) {
                float e0 = sE[m * DD + lane];
                float e1 = sE[m * DD + lane + 32];
                U64 b0 = pack2(e0, e0);
                U64 b1 = pack2(e1, e1);
                #pragma unroll
                for (int pe2 = 0; pe2 < 8; ++pe2) {    // 4 e per iter
                    ulonglong2 a = *reinterpret_cast<const ulonglong2*>(
                        &sH[m * HI + rg * 32 + 4 * pe2]);
                    dW2a[2 * pe2][0]     = ffma2(a.x, b0, dW2a[2 * pe2][0]);
                    dW2a[2 * pe2][1]     = ffma2(a.x, b1, dW2a[2 * pe2][1]);
                    dW2a[2 * pe2 + 1][0] = ffma2(a.y, b0, dW2a[2 * pe2 + 1][0]);
                    dW2a[2 * pe2 + 1][1] = ffma2(a.y, b1, dW2a[2 * pe2 + 1][1]);
                }
            }

            // ---- G4: dH = E @ W2^T ; dZ = dH * gelu'
            //      rows hr*16..+16, cols {c0, c0+128}, K-pairs over o
            {
                U64 g4[16][2];
                #pragma unroll
                for (int m = 0; m < 16; ++m) { g4[m][0] = 0ull; g4[m][1] = 0ull; }
                #pragma unroll 2
                for (int op2 = 0; op2 < 16; ++op2) {   // 4 o per iter
                    U64 b0a = ld64s(&sW2[c0 * 66 + 4 * op2]);
                    U64 b0b = ld64s(&sW2[c0 * 66 + 4 * op2 + 2]);
                    U64 b1a = ld64s(&sW2[(c0 + 128) * 66 + 4 * op2]);
                    U64 b1b = ld64s(&sW2[(c0 + 128) * 66 + 4 * op2 + 2]);
                    #pragma unroll
                    for (int m = 0; m < 16; ++m) {
                        ulonglong2 a = *reinterpret_cast<const ulonglong2*>(
                            &sE[(hr * 16 + m) * DD + 4 * op2]);
                        g4[m][0] = ffma2(a.x, b0a, g4[m][0]);
                        g4[m][0] = ffma2(a.y, b0b, g4[m][0]);
                        g4[m][1] = ffma2(a.x, b1a, g4[m][1]);
                        g4[m][1] = ffma2(a.y, b1b, g4[m][1]);
                    }
                }
                __syncthreads();   // all G3 reads of sH done before overwrite
                #pragma unroll
                for (int m = 0; m < 16; ++m) {
                    float2 s0 = unp2(g4[m][0]);
                    float2 s1 = unp2(g4[m][1]);
                    int idx = (hr * 16 + m) * HI + c0;
                    sH[idx]       = (s0.x + s0.y) * sGp[idx];
                    sH[idx + 128] = (s1.x + s1.y) * sGp[idx + 128];
                }
            }
            __syncthreads();

            // ---- G5: dW1 += X^T @ dZ  (d-pairs rg*4+pp, e = lane+32j)
            #pragma unroll 2
            for (int m = 0; m < MT; ++m) {
                ulonglong2 x01 = *reinterpret_cast<const ulonglong2*>(&sX[m * 64 + rg * 8]);
                ulonglong2 x23 = *reinterpret_cast<const ulonglong2*>(&sX[m * 64 + rg * 8 + 4]);
                #pragma unroll
                for (int j = 0; j < 8; ++j) {
                    float dz = sH[m * HI + lane + 32 * j];
                    U64 bz = pack2(dz, dz);
                    dW1a[0][j] = ffma2(x01.x, bz, dW1a[0][j]);
                    dW1a[1][j] = ffma2(x01.y, bz, dW1a[1][j]);
                    dW1a[2][j] = ffma2(x23.x, bz, dW1a[2][j]);
                    dW1a[3][j] = ffma2(x23.y, bz, dW1a[3][j]);
                }
            }
            __syncthreads();   // protect sX/sH/sE before next tile
        }

        // ---- SGD update (lr = 1.0)
        #pragma unroll
        for (int pp = 0; pp < 4; ++pp)
            #pragma unroll
            for (int j = 0; j < 8; ++j) {
                int addr = (rg * 4 + pp) * 512 + (lane + 32 * j) * 2;
                float2 w = unp2(ld64s(&sW1p[addr]));
                float2 g = unp2(dW1a[pp][j]);
                st64s(&sW1p[addr], pack2(w.x - g.x, w.y - g.y));
            }
        #pragma unroll
        for (int pe = 0; pe < 16; ++pe) {
            int e = rg * 32 + 2 * pe;
            #pragma unroll
            for (int c = 0; c < 2; ++c) {
                float2 g = unp2(dW2a[pe][c]);
                int o = lane + 32 * c;
                sW2[e * 66 + o]       -= g.x;
                sW2[(e + 1) * 66 + o] -= g.y;
            }
        }
        __syncthreads();
    }

    // Store final adapted weights: W1 pair-major, W2 pair-major (e-pairs)
    float* gw = g_W + (size_t)bh * (DD * HI + HI * DD);
    for (int i = tid; i < DD * HI; i += 256) gw[i] = sW1p[i];
    for (int i = tid; i < HI * DD; i += 256) {
        int e = i >> 6, o = i & 63;
        gw[DD * HI + (e >> 1) * 128 + o * 2 + (e & 1)] = sW2[e * 66 + o];
    }
}

// ---------------- eval: e-chunked fused MLP ---------------------------------
// smem (floats): sQ [64][64] @0 | sW1c [32 d2][64 e][2] @4096 |
//                sW2c [32 e2][64 o][2] @8192 | sHc [64][64] @12288
#define EOFF_Q   0
#define EOFF_W1C 4096
#define EOFF_W2C 8192
#define EOFF_HC  12288
#define EVAL_SMEM_BYTES (16384 * 4)

__global__ __launch_bounds__(256, 2)
void ttt_eval_kernel(const float* __restrict__ qq, float* __restrict__ out) {
    extern __shared__ float sm[];
    float* sQ   = sm + EOFF_Q;
    float* sW1c = sm + EOFF_W1C;
    float* sW2c = sm + EOFF_W2C;
    float* sHc  = sm + EOFF_HC;

    const int tile = blockIdx.x;     // 0..31
    const int bh   = blockIdx.y;     // 0..127
    const int b    = bh >> 4;
    const int h    = bh & 15;
    const int tid  = threadIdx.x;
    const int lane = tid & 31;
    const int rb   = tid >> 5;       // row block (8 rows)

    const float* gw  = g_W + (size_t)bh * (DD * HI + HI * DD);
    const float* gw2 = gw + DD * HI;
    const float* qb  = qq + ((size_t)bh * NS + tile * 64) * DD;

    // load Q tile (plain, float4)
    #pragma unroll
    for (int r = 0; r < 4; ++r) {
        int i4 = tid + 256 * r;
        *reinterpret_cast<float4*>(&sQ[i4 * 4]) =
            *reinterpret_cast<const float4*>(&qb[i4 * 4]);
    }

    U64 oacc[8][2];   // rows rb*8+i, cols {lane, lane+32}; K-pair over e
    #pragma unroll
    for (int i = 0; i < 8; ++i) { oacc[i][0] = 0ull; oacc[i][1] = 0ull; }

    for (int c = 0; c < 4; ++c) {
        __syncthreads();   // previous chunk consumers done (covers sQ fill too)
        // load W1 chunk: rows d2, 128 consecutive floats each
        #pragma unroll
        for (int r = 0; r < 4; ++r) {
            int i4 = tid + 256 * r;             // 1024 float4 = 4096 floats
            int d2 = i4 >> 5, off = (i4 & 31) * 4;
            *reinterpret_cast<float4*>(&sW1c[d2 * 128 + off]) =
                *reinterpret_cast<const float4*>(&gw[d2 * 512 + c * 128 + off]);
        }
        // load W2 chunk: contiguous 4096 floats
        #pragma unroll
        for (int r = 0; r < 4; ++r) {
            int i4 = tid + 256 * r;
            *reinterpret_cast<float4*>(&sW2c[i4 * 4]) =
                *reinterpret_cast<const float4*>(&gw2[c * 4096 + i4 * 4]);
        }
        __syncthreads();

        // Z chunk: rows rb*8..+8, e-cols {lane, lane+32}, K-pair over d
        {
            U64 zacc[8][2];
            #pragma unroll
            for (int i = 0; i < 8; ++i) { zacc[i][0] = 0ull; zacc[i][1] = 0ull; }
            #pragma unroll 4
            for (int dc = 0; dc < 16; ++dc) {    // 4 d per iter
                ulonglong2 aa[8];
                #pragma unroll
                for (int r = 0; r < 8; ++r)
                    aa[r] = *reinterpret_cast<const ulonglong2*>(
                        &sQ[(rb * 8 + r) * 64 + 4 * dc]);
                U64 b00 = ld64s(&sW1c[(2 * dc) * 128 + lane * 2]);
                U64 b01 = ld64s(&sW1c[(2 * dc + 1) * 128 + lane * 2]);
                U64 b10 = ld64s(&sW1c[(2 * dc) * 128 + (lane + 32) * 2]);
                U64 b11 = ld64s(&sW1c[(2 * dc + 1) * 128 + (lane + 32) * 2]);
                #pragma unroll
                for (int r = 0; r < 8; ++r) {
                    zacc[r][0] = ffma2(aa[r].x, b00, zacc[r][0]);
                    zacc[r][0] = ffma2(aa[r].y, b01, zacc[r][0]);
                    zacc[r][1] = ffma2(aa[r].x, b10, zacc[r][1]);
                    zacc[r][1] = ffma2(aa[r].y, b11, zacc[r][1]);
                }
            }
            #pragma unroll
            for (int r = 0; r < 8; ++r)
                #pragma unroll
                for (int g = 0; g < 2; ++g) {
                    float2 s = unp2(zacc[r][g]);
                    sHc[(rb * 8 + r) * 64 + lane + 32 * g] = gelu_f(s.x + s.y);
                }
        }
        __syncthreads();

        // O partial: rows rb*8..+8, cols {lane, lane+32}, K-pair over chunk e
        #pragma unroll 2
        for (int ec = 0; ec < 16; ++ec) {       // 4 e per iter (2 e-pairs)
            U64 b00 = ld64s(&sW2c[(2 * ec) * 128 + lane * 2]);
            U64 b01 = ld64s(&sW2c[(2 * ec + 1) * 128 + lane * 2]);
            U64 b10 = ld64s(&sW2c[(2 * ec) * 128 + (lane + 32) * 2]);
            U64 b11 = ld64s(&sW2c[(2 * ec + 1) * 128 + (lane + 32) * 2]);
            #pragma unroll
            for (int i = 0; i < 8; ++i) {
                ulonglong2 a = *reinterpret_cast<const ulonglong2*>(
                    &sHc[(rb * 8 + i) * 64 + 4 * ec]);
                oacc[i][0] = ffma2(a.x, b00, oacc[i][0]);
                oacc[i][0] = ffma2(a.y, b01, oacc[i][0]);
                oacc[i][1] = ffma2(a.x, b10, oacc[i][1]);
                oacc[i][1] = ffma2(a.y, b11, oacc[i][1]);
            }
        }
    }

    // write out[b, n, h*64 + o]
    #pragma unroll
    for (int i = 0; i < 8; ++i) {
        float2 s0 = unp2(oacc[i][0]);
        float2 s1 = unp2(oacc[i][1]);
        int n = tile * 64 + rb * 8 + i;
        size_t base = ((size_t)b * NS + n) * (NH * DD) + h * DD;
        out[base + lane]      = s0.x + s0.y;
        out[base + lane + 32] = s1.x + s1.y;
    }
}

extern "C" void kernel_launch(void* const* d_in, const int* in_sizes, int n_in,
                              void* d_out, int out_size) {
    const float* q  = (const float*)d_in[0];
    const float* k  = (const float*)d_in[1];
    const float* v  = (const float*)d_in[2];
    const float* W1 = (const float*)d_in[3];
    const float* W2 = (const float*)d_in[4];
    float* out = (float*)d_out;

    cudaFuncSetAttribute(ttt_train_kernel,
                         cudaFuncAttributeMaxDynamicSharedMemorySize, TRAIN_SMEM_BYTES);
    cudaFuncSetAttribute(ttt_eval_kernel,
                         cudaFuncAttributeMaxDynamicSharedMemorySize, EVAL_SMEM_BYTES);

    ttt_train_kernel<<<NB * NH, 256, TRAIN_SMEM_BYTES>>>(k, v, W1, W2);
    ttt_eval_kernel<<<dim3(NS / 64, NB * NH), 256, EVAL_SMEM_BYTES>>>(q, out);
}